// round 15
// baseline (speedup 1.0000x reference)
#include <cuda_runtime.h>
#include <cuda_fp16.h>
#include <cstdint>
#include <math.h>

#define BATCH 4
#define LEN 2048
#define DMODEL 1024
#define NH 8
#define DHEAD 128
#define MROWS (BATCH * LEN)

// fp16 GEMM operands
__device__ __half g_hA[MROWS * DMODEL];
__device__ __half g_hB[MROWS * DMODEL];
__device__ __half g_hWq[DMODEL * DMODEL];
__device__ __half g_hWk[DMODEL * DMODEL];
__device__ __half g_hWv[DMODEL * DMODEL];
__device__ __half g_hWo[DMODEL * DMODEL];
// fp16 attention operands
__device__ __half g_Qh[NH * BATCH * LEN * DHEAD];   // [h][b][l][d], pre-scaled
__device__ __half g_Kh[NH * BATCH * LEN * DHEAD];   // [h][b][l][d]
__device__ __half g_Vt[NH * BATCH * DHEAD * LEN];   // [h][b][d][l] transposed
__device__ __half g_ctx_h[BATCH * LEN * DMODEL];    // [b][l][h*128+d]

#define QSCL 0.08838834764831845f

// ---------------------------------------------------------------------------
__device__ __forceinline__ void mma_f16(float& d0, float& d1, float& d2,
                                        float& d3, uint32_t a0, uint32_t a1,
                                        uint32_t a2, uint32_t a3, uint32_t b0,
                                        uint32_t b1) {
    asm volatile(
        "mma.sync.aligned.m16n8k16.row.col.f32.f16.f16.f32 "
        "{%0,%1,%2,%3}, {%4,%5,%6,%7}, {%8,%9}, {%0,%1,%2,%3};"
        : "+f"(d0), "+f"(d1), "+f"(d2), "+f"(d3)
        : "r"(a0), "r"(a1), "r"(a2), "r"(a3), "r"(b0), "r"(b1));
}

__device__ __forceinline__ void ldsm_x4(uint32_t& r0, uint32_t& r1,
                                        uint32_t& r2, uint32_t& r3,
                                        uint32_t addr) {
    asm volatile(
        "ldmatrix.sync.aligned.m8n8.x4.shared.b16 {%0,%1,%2,%3}, [%4];"
        : "=r"(r0), "=r"(r1), "=r"(r2), "=r"(r3) : "r"(addr));
}

__device__ __forceinline__ uint32_t smem_u32(const void* p) {
    uint32_t a;
    asm("{ .reg .u64 t; cvta.to.shared.u64 t, %1; cvt.u32.u64 %0, t; }"
        : "=r"(a) : "l"(p));
    return a;
}

__device__ __forceinline__ uint32_t pack_h2(float a, float b) {
    const __half2 h = __floats2half2_rn(a, b);
    return *(const uint32_t*)&h;
}

#define CP_ASYNC16(dst_u32, src_ptr)                                          \
    asm volatile("cp.async.cg.shared.global [%0], [%1], 16;"                  \
                 :: "r"(dst_u32), "l"(src_ptr) : "memory")
#define CP_COMMIT() asm volatile("cp.async.commit_group;" ::: "memory")
#define CP_WAIT(n)  asm volatile("cp.async.wait_group %0;" :: "n"(n) : "memory")

// ===========================================================================
__global__ void __launch_bounds__(256)
cvt_f32_f16(const float* __restrict__ src, __half* __restrict__ dst, int n4)
{
    const int stride = gridDim.x * blockDim.x;
    for (int i = blockIdx.x * blockDim.x + threadIdx.x; i < n4; i += stride) {
        const float4 v = *(const float4*)(src + i * 4);
        __half2* d = (__half2*)(dst + i * 4);
        d[0] = __floats2half2_rn(v.x, v.y);
        d[1] = __floats2half2_rn(v.z, v.w);
    }
}

__global__ void __launch_bounds__(256)
cvt4_f32_f16(const float* __restrict__ s0, const float* __restrict__ s1,
             const float* __restrict__ s2, const float* __restrict__ s3,
             __half* __restrict__ d0, __half* __restrict__ d1,
             __half* __restrict__ d2, __half* __restrict__ d3, int n4)
{
    const float* src = blockIdx.y == 0 ? s0 : blockIdx.y == 1 ? s1
                     : blockIdx.y == 2 ? s2 : s3;
    __half* dst = blockIdx.y == 0 ? d0 : blockIdx.y == 1 ? d1
                : blockIdx.y == 2 ? d2 : d3;
    const int stride = gridDim.x * blockDim.x;
    for (int i = blockIdx.x * blockDim.x + threadIdx.x; i < n4; i += stride) {
        const float4 v = *(const float4*)(src + i * 4);
        __half2* d = (__half2*)(dst + i * 4);
        d[0] = __floats2half2_rn(v.x, v.y);
        d[1] = __floats2half2_rn(v.z, v.w);
    }
}

// ===========================================================================
// fp16 mma.sync NT-GEMM: CTA 128x128x32, 8 warps (2m x 4n), warp tile 64x32.
// 3-stage cp.async ring (R12/R14 mainloop). ldmatrix fragment loads.
// __launch_bounds__(256,3): cap regs at 85 => 3 CTAs/SM, 24 warps.
// MODEs: 0 fp32 out; 1 fp16 scatter; 2 fp16 scatter*QSCL;
//        3 fp16 transposed scatter via smem-staged coalesced stores.
// ===========================================================================
#define HSP 20
#define HSTG (128 * HSP)                 // u32 per operand per stage
#define HNIT (DMODEL / 32)               // 32
#define NSTG 3
#define GEMM_SMEM (NSTG * 2 * HSTG * (int)sizeof(uint32_t))   // 61440 B
#define TPITCH 136   // halves per row of transpose staging (272 B, 16B-mult)

template <int MODE>
__global__ void __launch_bounds__(256, 3)
gemm_h(const __half* __restrict__ A, const __half* __restrict__ W, void* Cv)
{
    extern __shared__ uint32_t sh[];
    const uint32_t sb = smem_u32(sh);

    const int tid = threadIdx.x;
    const int wid = tid >> 5;
    const int lane = tid & 31;
    const int wm = (wid >> 2) * 64;
    const int wn = (wid & 3) * 32;
    const int r = lane >> 2;
    const int c = lane & 3;
    const int m0 = blockIdx.x * 128;
    const int n0 = blockIdx.y * 128;

    const int lx = lane & 15;
    const int lhiA = (lane >> 4) * 4;
    const int l8 = lane & 7;
    const int lgB = (lane >> 4) * 8;
    const int lqB = ((lane >> 3) & 1) * 4;

    const int lrow = tid >> 1;
    const int lch = (tid & 1) * 2;

    const __half* Ag = A + (size_t)(m0 + lrow) * DMODEL + lch * 8;
    const __half* Wg = W + (size_t)(n0 + lrow) * DMODEL + lch * 8;
    const uint32_t dA0 = sb + (lrow * HSP + lch * 4) * 4;
    const uint32_t dW0 = sb + (HSTG + lrow * HSP + lch * 4) * 4;

    float acc[4][4][4];
#pragma unroll
    for (int i = 0; i < 4; i++)
#pragma unroll
        for (int j = 0; j < 4; j++)
#pragma unroll
            for (int q = 0; q < 4; q++) acc[i][j][q] = 0.0f;

    // prologue: fill stages 0,1,2
#pragma unroll
    for (int pre = 0; pre < NSTG; pre++) {
        const int k0 = pre * 32;
        const uint32_t so = pre * 2 * HSTG * 4;
        CP_ASYNC16(dA0 + so, Ag + k0);
        CP_ASYNC16(dA0 + so + 16, Ag + k0 + 8);
        CP_ASYNC16(dW0 + so, Wg + k0);
        CP_ASYNC16(dW0 + so + 16, Wg + k0 + 8);
        CP_COMMIT();
    }

    int stg = 0;
    for (int it = 0; it < HNIT; it++) {
        const uint32_t sA = sb + (stg * 2 * HSTG) * 4;
        const uint32_t sW = sA + HSTG * 4;

        CP_WAIT(2);
        __syncthreads();

#pragma unroll
        for (int ks = 0; ks < 2; ks++) {
            uint32_t af[4][4];
#pragma unroll
            for (int mt = 0; mt < 4; mt++) {
                const uint32_t a =
                    sA + ((wm + mt * 16 + lx) * HSP + ks * 8 + lhiA) * 4;
                ldsm_x4(af[mt][0], af[mt][1], af[mt][2], af[mt][3], a);
            }
            uint32_t bf[4][2];
#pragma unroll
            for (int p = 0; p < 2; p++) {
                const uint32_t a =
                    sW + ((wn + p * 16 + lgB + l8) * HSP + ks * 8 + lqB) * 4;
                ldsm_x4(bf[2 * p][0], bf[2 * p][1], bf[2 * p + 1][0],
                        bf[2 * p + 1][1], a);
            }
#pragma unroll
            for (int mt = 0; mt < 4; mt++)
#pragma unroll
                for (int nt = 0; nt < 4; nt++)
                    mma_f16(acc[mt][nt][0], acc[mt][nt][1], acc[mt][nt][2],
                            acc[mt][nt][3], af[mt][0], af[mt][1], af[mt][2],
                            af[mt][3], bf[nt][0], bf[nt][1]);
        }

        __syncthreads();
        const int nxt = it + NSTG;
        if (nxt < HNIT) {
            const int k0 = nxt * 32;
            const uint32_t so = stg * 2 * HSTG * 4;
            CP_ASYNC16(dA0 + so, Ag + k0);
            CP_ASYNC16(dA0 + so + 16, Ag + k0 + 8);
            CP_ASYNC16(dW0 + so, Wg + k0);
            CP_ASYNC16(dW0 + so + 16, Wg + k0 + 8);
        }
        CP_COMMIT();
        stg = (stg + 1 == NSTG) ? 0 : stg + 1;
    }

    if (MODE == 3) {
        // transpose via smem staging, then coalesced 16B stores along l
        CP_WAIT(0);
        __syncthreads();
        __half* ts = (__half*)sh;
#pragma unroll
        for (int mt = 0; mt < 4; mt++) {
#pragma unroll
            for (int half = 0; half < 2; half++) {
                const int ml = wm + mt * 16 + r + half * 8;
#pragma unroll
                for (int nt = 0; nt < 4; nt++) {
                    const int ncol = wn + nt * 8 + 2 * c;
                    ts[ncol * TPITCH + ml] =
                        __float2half_rn(acc[mt][nt][half * 2]);
                    ts[(ncol + 1) * TPITCH + ml] =
                        __float2half_rn(acc[mt][nt][half * 2 + 1]);
                }
            }
        }
        __syncthreads();
        const int hh = n0 >> 7;
        const int bb = m0 >> 11;
        const int ll0 = m0 & (LEN - 1);
        __half* base = (__half*)Cv + (size_t)(hh * BATCH + bb) * DHEAD * LEN;
#pragma unroll
        for (int it = 0; it < 8; it++) {
            const int f = tid + it * 256;
            const int d = f >> 4;
            const int ch = f & 15;
            const uint4 v = *(const uint4*)(ts + d * TPITCH + ch * 8);
            *(uint4*)(base + (size_t)d * LEN + ll0 + ch * 8) = v;
        }
        return;
    }

    // epilogue for MODEs 0/1/2
#pragma unroll
    for (int mt = 0; mt < 4; mt++) {
#pragma unroll
        for (int half = 0; half < 2; half++) {
            const int mrow = m0 + wm + mt * 16 + r + half * 8;
            const int bb = mrow >> 11;
            const int ll = mrow & (LEN - 1);
            const int hh = n0 >> 7;
#pragma unroll
            for (int nt = 0; nt < 4; nt++) {
                const int ncol = wn + nt * 8 + 2 * c;
                float v0 = acc[mt][nt][half * 2];
                float v1 = acc[mt][nt][half * 2 + 1];
                if (MODE == 0) {
                    float* dst = (float*)Cv + (size_t)mrow * DMODEL + n0;
                    *(float2*)(dst + ncol) = make_float2(v0, v1);
                } else {
                    if (MODE == 2) { v0 *= QSCL; v1 *= QSCL; }
                    __half* dst = (__half*)Cv +
                        (((size_t)(hh * BATCH + bb) * LEN + ll) << 7);
                    *(__half2*)(dst + ncol) = __floats2half2_rn(v0, v1);
                }
            }
        }
    }
}

// ===========================================================================
// Flash attention (exact R14 version): fp16 mma + ldmatrix + cp.async x2.
// ===========================================================================
#define KP2 68
#define VP2 36
#define STGH (64 * KP2 + 128 * VP2)
#define SMA_PS2 (2 * STGH)
#define SMA_TOT2 (SMA_PS2 + 128 * VP2)
#define SMEM_ATTN (SMA_TOT2 * (int)sizeof(uint32_t))

__global__ void __launch_bounds__(256)
attn_mma(const int* __restrict__ seq)
{
    extern __shared__ uint32_t sm[];
    const uint32_t sb = smem_u32(sm);
    uint32_t* Ps = sm + SMA_PS2;
    const uint32_t sbPs = sb + SMA_PS2 * 4;

    const int tid = threadIdx.x;
    const int wid = tid >> 5;
    const int lane = tid & 31;
    const int r = lane >> 2;
    const int c = lane & 3;
    const int qt = blockIdx.x, b = blockIdx.y, h = blockIdx.z;
    const int qbase = qt * 128;
    const int slen = seq[b];
    const int q0 = wid * 16;

    const int lx = lane & 15;
    const int lhiA = (lane >> 4) * 4;
    const int l8 = lane & 7;
    const int lgB = (lane >> 4) * 8;
    const int lqB = ((lane >> 3) & 1) * 4;

    __half* ctx = g_ctx_h + (size_t)b * LEN * DMODEL + (size_t)h * DHEAD;

    if (qbase >= slen) {
#pragma unroll
        for (int it = 0; it < 8; it++) {
            const int f = tid + it * 256;
            const int row = f >> 4;
            const int cu = (f & 15) * 8;
            *(uint4*)(ctx + (size_t)(qbase + row) * DMODEL + cu) =
                make_uint4(0, 0, 0, 0);
        }
        return;
    }

    const __half* Qg = g_Qh + (((size_t)h * BATCH + b) * LEN + qbase) * DHEAD;
    const __half* Kg = g_Kh + ((size_t)h * BATCH + b) * LEN * DHEAD;
    const __half* Vg = g_Vt + ((size_t)h * BATCH + b) * DHEAD * LEN;

    const int nkt = (slen + 63) >> 6;

#pragma unroll
    for (int it = 0; it < 8; it++) {
        const int f = tid + it * 256;
        const int row = f >> 4;
        const int ch = f & 15;
        CP_ASYNC16(sb + (row * KP2 + ch * 4) * 4,
                   Qg + (size_t)row * DHEAD + ch * 8);
    }
    CP_COMMIT();
    CP_WAIT(0);
    __syncthreads();

    uint32_t qf[8][4];
#pragma unroll
    for (int ks = 0; ks < 8; ks++) {
        const uint32_t a = sb + ((q0 + lx) * KP2 + ks * 8 + lhiA) * 4;
        ldsm_x4(qf[ks][0], qf[ks][1], qf[ks][2], qf[ks][3], a);
    }
    __syncthreads();

#pragma unroll 1
    for (int pre = 0; pre < 2; pre++) {
        if (pre < nkt) {
            const int kb = pre * 64;
            const uint32_t kbase = sb + (pre * STGH) * 4;
            const uint32_t vbase = kbase + (64 * KP2) * 4;
#pragma unroll
            for (int it = 0; it < 4; it++) {
                const int f = tid + it * 256;
                const int row = f >> 4;
                const int ch = f & 15;
                CP_ASYNC16(kbase + (row * KP2 + ch * 4) * 4,
                           Kg + (size_t)(kb + row) * DHEAD + ch * 8);
            }
#pragma unroll
            for (int it = 0; it < 4; it++) {
                const int f = tid + it * 256;
                const int d = f >> 3;
                const int ch = f & 7;
                CP_ASYNC16(vbase + (d * VP2 + ch * 4) * 4,
                           Vg + (size_t)d * LEN + kb + ch * 8);
            }
        }
        CP_COMMIT();
    }

    float o[16][4];
#pragma unroll
    for (int nt = 0; nt < 16; nt++)
#pragma unroll
        for (int q = 0; q < 4; q++) o[nt][q] = 0.0f;
    float m0v = -1e30f, m1v = -1e30f, l0 = 0.0f, l1 = 0.0f;

    for (int kt = 0; kt < nkt; kt++) {
        const int kb = kt * 64;
        const int stg = kt & 1;
        const uint32_t sK = sb + (stg * STGH) * 4;
        const uint32_t sV = sK + (64 * KP2) * 4;

        CP_WAIT(1);
        __syncthreads();

        float s[8][4];
#pragma unroll
        for (int nt = 0; nt < 8; nt++)
#pragma unroll
            for (int q = 0; q < 4; q++) s[nt][q] = 0.0f;

#pragma unroll
        for (int ks = 0; ks < 8; ks++) {
            uint32_t bf[8][2];
#pragma unroll
            for (int p = 0; p < 4; p++) {
                const uint32_t a =
                    sK + ((p * 16 + lgB + l8) * KP2 + ks * 8 + lqB) * 4;
                ldsm_x4(bf[2 * p][0], bf[2 * p][1], bf[2 * p + 1][0],
                        bf[2 * p + 1][1], a);
            }
#pragma unroll
            for (int nt = 0; nt < 8; nt++)
                mma_f16(s[nt][0], s[nt][1], s[nt][2], s[nt][3],
                        qf[ks][0], qf[ks][1], qf[ks][2], qf[ks][3],
                        bf[nt][0], bf[nt][1]);
        }

#pragma unroll
        for (int nt = 0; nt < 8; nt++) {
            const int j0 = kb + nt * 8 + 2 * c;
            if (j0 >= slen)     { s[nt][0] = -1e30f; s[nt][2] = -1e30f; }
            if (j0 + 1 >= slen) { s[nt][1] = -1e30f; s[nt][3] = -1e30f; }
        }

        float mt0 = -1e30f, mt1 = -1e30f;
#pragma unroll
        for (int nt = 0; nt < 8; nt++) {
            mt0 = fmaxf(mt0, fmaxf(s[nt][0], s[nt][1]));
            mt1 = fmaxf(mt1, fmaxf(s[nt][2], s[nt][3]));
        }
        mt0 = fmaxf(mt0, __shfl_xor_sync(0xffffffffu, mt0, 1));
        mt0 = fmaxf(mt0, __shfl_xor_sync(0xffffffffu, mt0, 2));
        mt1 = fmaxf(mt1, __shfl_xor_sync(0xffffffffu, mt1, 1));
        mt1 = fmaxf(mt1, __shfl_xor_sync(0xffffffffu, mt1, 2));

        const float mn0 = fmaxf(m0v, mt0);
        const float mn1 = fmaxf(m1v, mt1);
        const float sc0 = __expf(m0v - mn0);
        const float sc1 = __expf(m1v - mn1);
        m0v = mn0; m1v = mn1;

        float rs0 = 0.0f, rs1 = 0.0f;
#pragma unroll
        for (int nt = 0; nt < 8; nt++) {
            const float p0 = __expf(s[nt][0] - mn0);
            const float p1 = __expf(s[nt][1] - mn0);
            const float p2 = __expf(s[nt][2] - mn1);
            const float p3 = __expf(s[nt][3] - mn1);
            rs0 += p0 + p1;
            rs1 += p2 + p3;
            Ps[(q0 + r) * VP2 + nt * 4 + c] = pack_h2(p0, p1);
            Ps[(q0 + r + 8) * VP2 + nt * 4 + c] = pack_h2(p2, p3);
        }
        rs0 += __shfl_xor_sync(0xffffffffu, rs0, 1);
        rs0 += __shfl_xor_sync(0xffffffffu, rs0, 2);
        rs1 += __shfl_xor_sync(0xffffffffu, rs1, 1);
        rs1 += __shfl_xor_sync(0xffffffffu, rs1, 2);
        l0 = l0 * sc0 + rs0;
        l1 = l1 * sc1 + rs1;

#pragma unroll
        for (int nt = 0; nt < 16; nt++) {
            o[nt][0] *= sc0; o[nt][1] *= sc0;
            o[nt][2] *= sc1; o[nt][3] *= sc1;
        }
        __syncwarp();

#pragma unroll
        for (int ks = 0; ks < 4; ks++) {
            uint32_t af[4];
            {
                const uint32_t a =
                    sbPs + ((q0 + lx) * VP2 + ks * 8 + lhiA) * 4;
                ldsm_x4(af[0], af[1], af[2], af[3], a);
            }
#pragma unroll
            for (int p = 0; p < 8; p++) {
                uint32_t b0a, b0b, b1a, b1b;
                const uint32_t a =
                    sV + ((p * 16 + lgB + l8) * VP2 + ks * 8 + lqB) * 4;
                ldsm_x4(b0a, b0b, b1a, b1b, a);
                mma_f16(o[2 * p][0], o[2 * p][1], o[2 * p][2], o[2 * p][3],
                        af[0], af[1], af[2], af[3], b0a, b0b);
                mma_f16(o[2 * p + 1][0], o[2 * p + 1][1], o[2 * p + 1][2],
                        o[2 * p + 1][3], af[0], af[1], af[2], af[3], b1a, b1b);
            }
        }

        __syncthreads();

        const int nxt = kt + 2;
        if (nxt < nkt) {
            const int kb2 = nxt * 64;
            const uint32_t kbase = sb + (stg * STGH) * 4;
            const uint32_t vbase = kbase + (64 * KP2) * 4;
#pragma unroll
            for (int it = 0; it < 4; it++) {
                const int f = tid + it * 256;
                const int row = f >> 4;
                const int ch = f & 15;
                CP_ASYNC16(kbase + (row * KP2 + ch * 4) * 4,
                           Kg + (size_t)(kb2 + row) * DHEAD + ch * 8);
            }
#pragma unroll
            for (int it = 0; it < 4; it++) {
                const int f = tid + it * 256;
                const int d = f >> 3;
                const int ch = f & 7;
                CP_ASYNC16(vbase + (d * VP2 + ch * 4) * 4,
                           Vg + (size_t)d * LEN + kb2 + ch * 8);
            }
        }
        CP_COMMIT();
    }

    const int qr0 = qbase + q0 + r;
    const int qr1 = qr0 + 8;
    const float inv0 = (qr0 < slen) ? (1.0f / l0) : 0.0f;
    const float inv1 = (qr1 < slen) ? (1.0f / l1) : 0.0f;
#pragma unroll
    for (int nt = 0; nt < 16; nt++) {
        const int col = nt * 8 + 2 * c;
        *(__half2*)(ctx + (size_t)qr0 * DMODEL + col) =
            __floats2half2_rn(o[nt][0] * inv0, o[nt][1] * inv0);
        *(__half2*)(ctx + (size_t)qr1 * DMODEL + col) =
            __floats2half2_rn(o[nt][2] * inv1, o[nt][3] * inv1);
    }
}

// ===========================================================================
extern "C" void kernel_launch(void* const* d_in, const int* in_sizes, int n_in,
                              void* d_out, int out_size)
{
    (void)in_sizes; (void)n_in; (void)out_size;
    const float* queries = (const float*)d_in[0];
    const float* keys    = (const float*)d_in[1];
    const int*   seqlen  = (const int*)d_in[2];
    const float* Wq      = (const float*)d_in[3];
    const float* Wk      = (const float*)d_in[4];
    const float* Wv      = (const float*)d_in[5];
    const float* Wo      = (const float*)d_in[6];
    float* out = (float*)d_out;

    void *phA, *phB, *phWq, *phWk, *phWv, *phWo, *pQh, *pKh, *pVt, *pCtxH;
    cudaGetSymbolAddress(&phA, g_hA);
    cudaGetSymbolAddress(&phB, g_hB);
    cudaGetSymbolAddress(&phWq, g_hWq);
    cudaGetSymbolAddress(&phWk, g_hWk);
    cudaGetSymbolAddress(&phWv, g_hWv);
    cudaGetSymbolAddress(&phWo, g_hWo);
    cudaGetSymbolAddress(&pQh, g_Qh);
    cudaGetSymbolAddress(&pKh, g_Kh);
    cudaGetSymbolAddress(&pVt, g_Vt);
    cudaGetSymbolAddress(&pCtxH, g_ctx_h);

    cudaFuncSetAttribute(gemm_h<0>,
                         cudaFuncAttributeMaxDynamicSharedMemorySize, GEMM_SMEM);
    cudaFuncSetAttribute(gemm_h<1>,
                         cudaFuncAttributeMaxDynamicSharedMemorySize, GEMM_SMEM);
    cudaFuncSetAttribute(gemm_h<2>,
                         cudaFuncAttributeMaxDynamicSharedMemorySize, GEMM_SMEM);
    cudaFuncSetAttribute(gemm_h<3>,
                         cudaFuncAttributeMaxDynamicSharedMemorySize, GEMM_SMEM);
    cudaFuncSetAttribute(attn_mma,
                         cudaFuncAttributeMaxDynamicSharedMemorySize, SMEM_ATTN);

    const int nBig4 = MROWS * DMODEL / 4;
    const int nW4 = DMODEL * DMODEL / 4;
    cvt_f32_f16<<<512, 256>>>(queries, (__half*)phA, nBig4);
    cvt_f32_f16<<<512, 256>>>(keys,    (__half*)phB, nBig4);
    cvt4_f32_f16<<<dim3(128, 4), 256>>>(Wq, Wk, Wv, Wo,
                                        (__half*)phWq, (__half*)phWk,
                                        (__half*)phWv, (__half*)phWo, nW4);

    const dim3 gg(MROWS / 128, DMODEL / 128);
    gemm_h<2><<<gg, 256, GEMM_SMEM>>>((const __half*)phA, (const __half*)phWq, pQh);
    gemm_h<1><<<gg, 256, GEMM_SMEM>>>((const __half*)phB, (const __half*)phWk, pKh);
    gemm_h<3><<<gg, 256, GEMM_SMEM>>>((const __half*)phB, (const __half*)phWv, pVt);

    attn_mma<<<dim3(LEN / 128, BATCH, NH), 256, SMEM_ATTN>>>(seqlen);

    gemm_h<0><<<gg, 256, GEMM_SMEM>>>((const __half*)pCtxH, (const __half*)phWo, out);
}

// round 16
// speedup vs baseline: 1.5396x; 1.5396x over previous
#include <cuda_runtime.h>
#include <cuda_fp16.h>
#include <cstdint>
#include <math.h>

#define BATCH 4
#define LEN 2048
#define DMODEL 1024
#define NH 8
#define DHEAD 128
#define MROWS (BATCH * LEN)

// fp16 GEMM operands
__device__ __half g_hA[MROWS * DMODEL];
__device__ __half g_hB[MROWS * DMODEL];
__device__ __half g_hWq[DMODEL * DMODEL];
__device__ __half g_hWk[DMODEL * DMODEL];
__device__ __half g_hWv[DMODEL * DMODEL];
__device__ __half g_hWo[DMODEL * DMODEL];
// fp16 attention operands
__device__ __half g_Qh[NH * BATCH * LEN * DHEAD];   // [h][b][l][d], pre-scaled
__device__ __half g_Kh[NH * BATCH * LEN * DHEAD];   // [h][b][l][d]
__device__ __half g_Vt[NH * BATCH * DHEAD * LEN];   // [h][b][d][l] transposed
__device__ __half g_ctx_h[BATCH * LEN * DMODEL];    // [b][l][h*128+d]

#define QSCL 0.08838834764831845f

// ---------------------------------------------------------------------------
__device__ __forceinline__ void mma_f16(float& d0, float& d1, float& d2,
                                        float& d3, uint32_t a0, uint32_t a1,
                                        uint32_t a2, uint32_t a3, uint32_t b0,
                                        uint32_t b1) {
    asm volatile(
        "mma.sync.aligned.m16n8k16.row.col.f32.f16.f16.f32 "
        "{%0,%1,%2,%3}, {%4,%5,%6,%7}, {%8,%9}, {%0,%1,%2,%3};"
        : "+f"(d0), "+f"(d1), "+f"(d2), "+f"(d3)
        : "r"(a0), "r"(a1), "r"(a2), "r"(a3), "r"(b0), "r"(b1));
}

__device__ __forceinline__ void ldsm_x4(uint32_t& r0, uint32_t& r1,
                                        uint32_t& r2, uint32_t& r3,
                                        uint32_t addr) {
    asm volatile(
        "ldmatrix.sync.aligned.m8n8.x4.shared.b16 {%0,%1,%2,%3}, [%4];"
        : "=r"(r0), "=r"(r1), "=r"(r2), "=r"(r3) : "r"(addr));
}

__device__ __forceinline__ uint32_t smem_u32(const void* p) {
    uint32_t a;
    asm("{ .reg .u64 t; cvta.to.shared.u64 t, %1; cvt.u32.u64 %0, t; }"
        : "=r"(a) : "l"(p));
    return a;
}

__device__ __forceinline__ uint32_t pack_h2(float a, float b) {
    const __half2 h = __floats2half2_rn(a, b);
    return *(const uint32_t*)&h;
}

#define CP_ASYNC16(dst_u32, src_ptr)                                          \
    asm volatile("cp.async.cg.shared.global [%0], [%1], 16;"                  \
                 :: "r"(dst_u32), "l"(src_ptr) : "memory")
#define CP_COMMIT() asm volatile("cp.async.commit_group;" ::: "memory")
#define CP_WAIT(n)  asm volatile("cp.async.wait_group %0;" :: "n"(n) : "memory")

// ===========================================================================
__global__ void __launch_bounds__(256)
cvt_f32_f16(const float* __restrict__ src, __half* __restrict__ dst, int n4)
{
    const int stride = gridDim.x * blockDim.x;
    for (int i = blockIdx.x * blockDim.x + threadIdx.x; i < n4; i += stride) {
        const float4 v = *(const float4*)(src + i * 4);
        __half2* d = (__half2*)(dst + i * 4);
        d[0] = __floats2half2_rn(v.x, v.y);
        d[1] = __floats2half2_rn(v.z, v.w);
    }
}

__global__ void __launch_bounds__(256)
cvt4_f32_f16(const float* __restrict__ s0, const float* __restrict__ s1,
             const float* __restrict__ s2, const float* __restrict__ s3,
             __half* __restrict__ d0, __half* __restrict__ d1,
             __half* __restrict__ d2, __half* __restrict__ d3, int n4)
{
    const float* src = blockIdx.y == 0 ? s0 : blockIdx.y == 1 ? s1
                     : blockIdx.y == 2 ? s2 : s3;
    __half* dst = blockIdx.y == 0 ? d0 : blockIdx.y == 1 ? d1
                : blockIdx.y == 2 ? d2 : d3;
    const int stride = gridDim.x * blockDim.x;
    for (int i = blockIdx.x * blockDim.x + threadIdx.x; i < n4; i += stride) {
        const float4 v = *(const float4*)(src + i * 4);
        __half2* d = (__half2*)(dst + i * 4);
        d[0] = __floats2half2_rn(v.x, v.y);
        d[1] = __floats2half2_rn(v.z, v.w);
    }
}

// ===========================================================================
// Shared GEMM pieces (R14 mainloop, measured best).
// ===========================================================================
#define HSP 20
#define HSTG (128 * HSP)                 // u32 per operand per stage
#define HNIT (DMODEL / 32)               // 32
#define NSTG 3
#define GEMM_SMEM (NSTG * 2 * HSTG * (int)sizeof(uint32_t))   // 61440 B
#define TPITCH 136

// Mainloop: accumulates the 128x128 tile of A@W^T at (m0,n0) into acc.
__device__ __forceinline__ void gemm_mainloop(
    const __half* __restrict__ A, const __half* __restrict__ W,
    uint32_t sb, int m0, int n0, int tid, float acc[4][4][4])
{
    const int wid = tid >> 5;
    const int lane = tid & 31;
    const int wm = (wid >> 2) * 64;
    const int wn = (wid & 3) * 32;
    const int lx = lane & 15;
    const int lhiA = (lane >> 4) * 4;
    const int l8 = lane & 7;
    const int lgB = (lane >> 4) * 8;
    const int lqB = ((lane >> 3) & 1) * 4;

    const int lrow = tid >> 1;
    const int lch = (tid & 1) * 2;

    const __half* Ag = A + (size_t)(m0 + lrow) * DMODEL + lch * 8;
    const __half* Wg = W + (size_t)(n0 + lrow) * DMODEL + lch * 8;
    const uint32_t dA0 = sb + (lrow * HSP + lch * 4) * 4;
    const uint32_t dW0 = sb + (HSTG + lrow * HSP + lch * 4) * 4;

#pragma unroll
    for (int pre = 0; pre < NSTG; pre++) {
        const int k0 = pre * 32;
        const uint32_t so = pre * 2 * HSTG * 4;
        CP_ASYNC16(dA0 + so, Ag + k0);
        CP_ASYNC16(dA0 + so + 16, Ag + k0 + 8);
        CP_ASYNC16(dW0 + so, Wg + k0);
        CP_ASYNC16(dW0 + so + 16, Wg + k0 + 8);
        CP_COMMIT();
    }

    int stg = 0;
    for (int it = 0; it < HNIT; it++) {
        const uint32_t sA = sb + (stg * 2 * HSTG) * 4;
        const uint32_t sW = sA + HSTG * 4;

        CP_WAIT(2);
        __syncthreads();

#pragma unroll
        for (int ks = 0; ks < 2; ks++) {
            uint32_t af[4][4];
#pragma unroll
            for (int mt = 0; mt < 4; mt++) {
                const uint32_t a =
                    sA + ((wm + mt * 16 + lx) * HSP + ks * 8 + lhiA) * 4;
                ldsm_x4(af[mt][0], af[mt][1], af[mt][2], af[mt][3], a);
            }
            uint32_t bf[4][2];
#pragma unroll
            for (int p = 0; p < 2; p++) {
                const uint32_t a =
                    sW + ((wn + p * 16 + lgB + l8) * HSP + ks * 8 + lqB) * 4;
                ldsm_x4(bf[2 * p][0], bf[2 * p][1], bf[2 * p + 1][0],
                        bf[2 * p + 1][1], a);
            }
#pragma unroll
            for (int mt = 0; mt < 4; mt++)
#pragma unroll
                for (int nt = 0; nt < 4; nt++)
                    mma_f16(acc[mt][nt][0], acc[mt][nt][1], acc[mt][nt][2],
                            acc[mt][nt][3], af[mt][0], af[mt][1], af[mt][2],
                            af[mt][3], bf[nt][0], bf[nt][1]);
        }

        __syncthreads();
        const int nxt = it + NSTG;
        if (nxt < HNIT) {
            const int k0 = nxt * 32;
            const uint32_t so = stg * 2 * HSTG * 4;
            CP_ASYNC16(dA0 + so, Ag + k0);
            CP_ASYNC16(dA0 + so + 16, Ag + k0 + 8);
            CP_ASYNC16(dW0 + so, Wg + k0);
            CP_ASYNC16(dW0 + so + 16, Wg + k0 + 8);
        }
        CP_COMMIT();
        stg = (stg + 1 == NSTG) ? 0 : stg + 1;
    }
}

// ===========================================================================
// Fused Q/K/V projection GEMM: one launch, grid.z selects operand set.
//  z=0: Qh = (queries @ Wq^T) * QSCL, scatter [h][b][l][d]
//  z=1: Kh =  keys   @ Wk^T,          scatter [h][b][l][d]
//  z=2: Vt =  keys   @ Wv^T,          TRANSPOSED scatter [h][b][d][l]
// ===========================================================================
__global__ void __launch_bounds__(256)
gemm_qkv(const __half* __restrict__ Aq, const __half* __restrict__ Ak,
         const __half* __restrict__ Wq, const __half* __restrict__ Wk,
         const __half* __restrict__ Wv,
         __half* __restrict__ Qh, __half* __restrict__ Kh,
         __half* __restrict__ Vt)
{
    extern __shared__ uint32_t sh[];
    const uint32_t sb = smem_u32(sh);

    const int tid = threadIdx.x;
    const int wid = tid >> 5;
    const int lane = tid & 31;
    const int wm = (wid >> 2) * 64;
    const int wn = (wid & 3) * 32;
    const int r = lane >> 2;
    const int c = lane & 3;
    const int m0 = blockIdx.x * 128;
    const int n0 = blockIdx.y * 128;
    const int z = blockIdx.z;

    const __half* A = (z == 0) ? Aq : Ak;
    const __half* W = (z == 0) ? Wq : (z == 1) ? Wk : Wv;

    float acc[4][4][4];
#pragma unroll
    for (int i = 0; i < 4; i++)
#pragma unroll
        for (int j = 0; j < 4; j++)
#pragma unroll
            for (int q = 0; q < 4; q++) acc[i][j][q] = 0.0f;

    gemm_mainloop(A, W, sb, m0, n0, tid, acc);

    const int hh = n0 >> 7;
    const int bb = m0 >> 11;

    if (z == 2) {
        // V: transpose via smem staging, coalesced 16B stores along l
        CP_WAIT(0);
        __syncthreads();
        __half* ts = (__half*)sh;
#pragma unroll
        for (int mt = 0; mt < 4; mt++) {
#pragma unroll
            for (int half = 0; half < 2; half++) {
                const int ml = wm + mt * 16 + r + half * 8;
#pragma unroll
                for (int nt = 0; nt < 4; nt++) {
                    const int ncol = wn + nt * 8 + 2 * c;
                    ts[ncol * TPITCH + ml] =
                        __float2half_rn(acc[mt][nt][half * 2]);
                    ts[(ncol + 1) * TPITCH + ml] =
                        __float2half_rn(acc[mt][nt][half * 2 + 1]);
                }
            }
        }
        __syncthreads();
        const int ll0 = m0 & (LEN - 1);
        __half* base = Vt + (size_t)(hh * BATCH + bb) * DHEAD * LEN;
#pragma unroll
        for (int it = 0; it < 8; it++) {
            const int f = tid + it * 256;
            const int d = f >> 4;
            const int ch = f & 15;
            const uint4 v = *(const uint4*)(ts + d * TPITCH + ch * 8);
            *(uint4*)(base + (size_t)d * LEN + ll0 + ch * 8) = v;
        }
        return;
    }

    // Q/K: scatter [h][b][l][d] (Q scaled)
    const float scl = (z == 0) ? QSCL : 1.0f;
    __half* C = (z == 0) ? Qh : Kh;
#pragma unroll
    for (int mt = 0; mt < 4; mt++) {
#pragma unroll
        for (int half = 0; half < 2; half++) {
            const int mrow = m0 + wm + mt * 16 + r + half * 8;
            const int ll = mrow & (LEN - 1);
            __half* dst =
                C + (((size_t)(hh * BATCH + bb) * LEN + ll) << 7);
#pragma unroll
            for (int nt = 0; nt < 4; nt++) {
                const int ncol = wn + nt * 8 + 2 * c;
                *(__half2*)(dst + ncol) = __floats2half2_rn(
                    acc[mt][nt][half * 2] * scl,
                    acc[mt][nt][half * 2 + 1] * scl);
            }
        }
    }
}

// Final GEMM: out = ctx @ Wo^T, fp32 row-major.
__global__ void __launch_bounds__(256)
gemm_out(const __half* __restrict__ A, const __half* __restrict__ W,
         float* __restrict__ C)
{
    extern __shared__ uint32_t sh[];
    const uint32_t sb = smem_u32(sh);

    const int tid = threadIdx.x;
    const int wid = tid >> 5;
    const int lane = tid & 31;
    const int wm = (wid >> 2) * 64;
    const int wn = (wid & 3) * 32;
    const int r = lane >> 2;
    const int c = lane & 3;
    const int m0 = blockIdx.x * 128;
    const int n0 = blockIdx.y * 128;

    float acc[4][4][4];
#pragma unroll
    for (int i = 0; i < 4; i++)
#pragma unroll
        for (int j = 0; j < 4; j++)
#pragma unroll
            for (int q = 0; q < 4; q++) acc[i][j][q] = 0.0f;

    gemm_mainloop(A, W, sb, m0, n0, tid, acc);

#pragma unroll
    for (int mt = 0; mt < 4; mt++) {
#pragma unroll
        for (int half = 0; half < 2; half++) {
            const int mrow = m0 + wm + mt * 16 + r + half * 8;
            float* dst = C + (size_t)mrow * DMODEL + n0;
#pragma unroll
            for (int nt = 0; nt < 4; nt++) {
                const int ncol = wn + nt * 8 + 2 * c;
                *(float2*)(dst + ncol) = make_float2(
                    acc[mt][nt][half * 2], acc[mt][nt][half * 2 + 1]);
            }
        }
    }
}

// ===========================================================================
// Flash attention (exact R14 version): fp16 mma + ldmatrix + cp.async x2.
// ===========================================================================
#define KP2 68
#define VP2 36
#define STGH (64 * KP2 + 128 * VP2)
#define SMA_PS2 (2 * STGH)
#define SMA_TOT2 (SMA_PS2 + 128 * VP2)
#define SMEM_ATTN (SMA_TOT2 * (int)sizeof(uint32_t))

__global__ void __launch_bounds__(256)
attn_mma(const int* __restrict__ seq)
{
    extern __shared__ uint32_t sm[];
    const uint32_t sb = smem_u32(sm);
    uint32_t* Ps = sm + SMA_PS2;
    const uint32_t sbPs = sb + SMA_PS2 * 4;

    const int tid = threadIdx.x;
    const int wid = tid >> 5;
    const int lane = tid & 31;
    const int r = lane >> 2;
    const int c = lane & 3;
    const int qt = blockIdx.x, b = blockIdx.y, h = blockIdx.z;
    const int qbase = qt * 128;
    const int slen = seq[b];
    const int q0 = wid * 16;

    const int lx = lane & 15;
    const int lhiA = (lane >> 4) * 4;
    const int l8 = lane & 7;
    const int lgB = (lane >> 4) * 8;
    const int lqB = ((lane >> 3) & 1) * 4;

    __half* ctx = g_ctx_h + (size_t)b * LEN * DMODEL + (size_t)h * DHEAD;

    if (qbase >= slen) {
#pragma unroll
        for (int it = 0; it < 8; it++) {
            const int f = tid + it * 256;
            const int row = f >> 4;
            const int cu = (f & 15) * 8;
            *(uint4*)(ctx + (size_t)(qbase + row) * DMODEL + cu) =
                make_uint4(0, 0, 0, 0);
        }
        return;
    }

    const __half* Qg = g_Qh + (((size_t)h * BATCH + b) * LEN + qbase) * DHEAD;
    const __half* Kg = g_Kh + ((size_t)h * BATCH + b) * LEN * DHEAD;
    const __half* Vg = g_Vt + ((size_t)h * BATCH + b) * DHEAD * LEN;

    const int nkt = (slen + 63) >> 6;

#pragma unroll
    for (int it = 0; it < 8; it++) {
        const int f = tid + it * 256;
        const int row = f >> 4;
        const int ch = f & 15;
        CP_ASYNC16(sb + (row * KP2 + ch * 4) * 4,
                   Qg + (size_t)row * DHEAD + ch * 8);
    }
    CP_COMMIT();
    CP_WAIT(0);
    __syncthreads();

    uint32_t qf[8][4];
#pragma unroll
    for (int ks = 0; ks < 8; ks++) {
        const uint32_t a = sb + ((q0 + lx) * KP2 + ks * 8 + lhiA) * 4;
        ldsm_x4(qf[ks][0], qf[ks][1], qf[ks][2], qf[ks][3], a);
    }
    __syncthreads();

#pragma unroll 1
    for (int pre = 0; pre < 2; pre++) {
        if (pre < nkt) {
            const int kb = pre * 64;
            const uint32_t kbase = sb + (pre * STGH) * 4;
            const uint32_t vbase = kbase + (64 * KP2) * 4;
#pragma unroll
            for (int it = 0; it < 4; it++) {
                const int f = tid + it * 256;
                const int row = f >> 4;
                const int ch = f & 15;
                CP_ASYNC16(kbase + (row * KP2 + ch * 4) * 4,
                           Kg + (size_t)(kb + row) * DHEAD + ch * 8);
            }
#pragma unroll
            for (int it = 0; it < 4; it++) {
                const int f = tid + it * 256;
                const int d = f >> 3;
                const int ch = f & 7;
                CP_ASYNC16(vbase + (d * VP2 + ch * 4) * 4,
                           Vg + (size_t)d * LEN + kb + ch * 8);
            }
        }
        CP_COMMIT();
    }

    float o[16][4];
#pragma unroll
    for (int nt = 0; nt < 16; nt++)
#pragma unroll
        for (int q = 0; q < 4; q++) o[nt][q] = 0.0f;
    float m0v = -1e30f, m1v = -1e30f, l0 = 0.0f, l1 = 0.0f;

    for (int kt = 0; kt < nkt; kt++) {
        const int kb = kt * 64;
        const int stg = kt & 1;
        const uint32_t sK = sb + (stg * STGH) * 4;
        const uint32_t sV = sK + (64 * KP2) * 4;

        CP_WAIT(1);
        __syncthreads();

        float s[8][4];
#pragma unroll
        for (int nt = 0; nt < 8; nt++)
#pragma unroll
            for (int q = 0; q < 4; q++) s[nt][q] = 0.0f;

#pragma unroll
        for (int ks = 0; ks < 8; ks++) {
            uint32_t bf[8][2];
#pragma unroll
            for (int p = 0; p < 4; p++) {
                const uint32_t a =
                    sK + ((p * 16 + lgB + l8) * KP2 + ks * 8 + lqB) * 4;
                ldsm_x4(bf[2 * p][0], bf[2 * p][1], bf[2 * p + 1][0],
                        bf[2 * p + 1][1], a);
            }
#pragma unroll
            for (int nt = 0; nt < 8; nt++)
                mma_f16(s[nt][0], s[nt][1], s[nt][2], s[nt][3],
                        qf[ks][0], qf[ks][1], qf[ks][2], qf[ks][3],
                        bf[nt][0], bf[nt][1]);
        }

#pragma unroll
        for (int nt = 0; nt < 8; nt++) {
            const int j0 = kb + nt * 8 + 2 * c;
            if (j0 >= slen)     { s[nt][0] = -1e30f; s[nt][2] = -1e30f; }
            if (j0 + 1 >= slen) { s[nt][1] = -1e30f; s[nt][3] = -1e30f; }
        }

        float mt0 = -1e30f, mt1 = -1e30f;
#pragma unroll
        for (int nt = 0; nt < 8; nt++) {
            mt0 = fmaxf(mt0, fmaxf(s[nt][0], s[nt][1]));
            mt1 = fmaxf(mt1, fmaxf(s[nt][2], s[nt][3]));
        }
        mt0 = fmaxf(mt0, __shfl_xor_sync(0xffffffffu, mt0, 1));
        mt0 = fmaxf(mt0, __shfl_xor_sync(0xffffffffu, mt0, 2));
        mt1 = fmaxf(mt1, __shfl_xor_sync(0xffffffffu, mt1, 1));
        mt1 = fmaxf(mt1, __shfl_xor_sync(0xffffffffu, mt1, 2));

        const float mn0 = fmaxf(m0v, mt0);
        const float mn1 = fmaxf(m1v, mt1);
        const float sc0 = __expf(m0v - mn0);
        const float sc1 = __expf(m1v - mn1);
        m0v = mn0; m1v = mn1;

        float rs0 = 0.0f, rs1 = 0.0f;
#pragma unroll
        for (int nt = 0; nt < 8; nt++) {
            const float p0 = __expf(s[nt][0] - mn0);
            const float p1 = __expf(s[nt][1] - mn0);
            const float p2 = __expf(s[nt][2] - mn1);
            const float p3 = __expf(s[nt][3] - mn1);
            rs0 += p0 + p1;
            rs1 += p2 + p3;
            Ps[(q0 + r) * VP2 + nt * 4 + c] = pack_h2(p0, p1);
            Ps[(q0 + r + 8) * VP2 + nt * 4 + c] = pack_h2(p2, p3);
        }
        rs0 += __shfl_xor_sync(0xffffffffu, rs0, 1);
        rs0 += __shfl_xor_sync(0xffffffffu, rs0, 2);
        rs1 += __shfl_xor_sync(0xffffffffu, rs1, 1);
        rs1 += __shfl_xor_sync(0xffffffffu, rs1, 2);
        l0 = l0 * sc0 + rs0;
        l1 = l1 * sc1 + rs1;

#pragma unroll
        for (int nt = 0; nt < 16; nt++) {
            o[nt][0] *= sc0; o[nt][1] *= sc0;
            o[nt][2] *= sc1; o[nt][3] *= sc1;
        }
        __syncwarp();

#pragma unroll
        for (int ks = 0; ks < 4; ks++) {
            uint32_t af[4];
            {
                const uint32_t a =
                    sbPs + ((q0 + lx) * VP2 + ks * 8 + lhiA) * 4;
                ldsm_x4(af[0], af[1], af[2], af[3], a);
            }
#pragma unroll
            for (int p = 0; p < 8; p++) {
                uint32_t b0a, b0b, b1a, b1b;
                const uint32_t a =
                    sV + ((p * 16 + lgB + l8) * VP2 + ks * 8 + lqB) * 4;
                ldsm_x4(b0a, b0b, b1a, b1b, a);
                mma_f16(o[2 * p][0], o[2 * p][1], o[2 * p][2], o[2 * p][3],
                        af[0], af[1], af[2], af[3], b0a, b0b);
                mma_f16(o[2 * p + 1][0], o[2 * p + 1][1], o[2 * p + 1][2],
                        o[2 * p + 1][3], af[0], af[1], af[2], af[3], b1a, b1b);
            }
        }

        __syncthreads();

        const int nxt = kt + 2;
        if (nxt < nkt) {
            const int kb2 = nxt * 64;
            const uint32_t kbase = sb + (stg * STGH) * 4;
            const uint32_t vbase = kbase + (64 * KP2) * 4;
#pragma unroll
            for (int it = 0; it < 4; it++) {
                const int f = tid + it * 256;
                const int row = f >> 4;
                const int ch = f & 15;
                CP_ASYNC16(kbase + (row * KP2 + ch * 4) * 4,
                           Kg + (size_t)(kb2 + row) * DHEAD + ch * 8);
            }
#pragma unroll
            for (int it = 0; it < 4; it++) {
                const int f = tid + it * 256;
                const int d = f >> 3;
                const int ch = f & 7;
                CP_ASYNC16(vbase + (d * VP2 + ch * 4) * 4,
                           Vg + (size_t)d * LEN + kb2 + ch * 8);
            }
        }
        CP_COMMIT();
    }

    const int qr0 = qbase + q0 + r;
    const int qr1 = qr0 + 8;
    const float inv0 = (qr0 < slen) ? (1.0f / l0) : 0.0f;
    const float inv1 = (qr1 < slen) ? (1.0f / l1) : 0.0f;
#pragma unroll
    for (int nt = 0; nt < 16; nt++) {
        const int col = nt * 8 + 2 * c;
        *(__half2*)(ctx + (size_t)qr0 * DMODEL + col) =
            __floats2half2_rn(o[nt][0] * inv0, o[nt][1] * inv0);
        *(__half2*)(ctx + (size_t)qr1 * DMODEL + col) =
            __floats2half2_rn(o[nt][2] * inv1, o[nt][3] * inv1);
    }
}

// ===========================================================================
extern "C" void kernel_launch(void* const* d_in, const int* in_sizes, int n_in,
                              void* d_out, int out_size)
{
    (void)in_sizes; (void)n_in; (void)out_size;
    const float* queries = (const float*)d_in[0];
    const float* keys    = (const float*)d_in[1];
    const int*   seqlen  = (const int*)d_in[2];
    const float* Wq      = (const float*)d_in[3];
    const float* Wk      = (const float*)d_in[4];
    const float* Wv      = (const float*)d_in[5];
    const float* Wo      = (const float*)d_in[6];
    float* out = (float*)d_out;

    void *phA, *phB, *phWq, *phWk, *phWv, *phWo, *pQh, *pKh, *pVt, *pCtxH;
    cudaGetSymbolAddress(&phA, g_hA);
    cudaGetSymbolAddress(&phB, g_hB);
    cudaGetSymbolAddress(&phWq, g_hWq);
    cudaGetSymbolAddress(&phWk, g_hWk);
    cudaGetSymbolAddress(&phWv, g_hWv);
    cudaGetSymbolAddress(&phWo, g_hWo);
    cudaGetSymbolAddress(&pQh, g_Qh);
    cudaGetSymbolAddress(&pKh, g_Kh);
    cudaGetSymbolAddress(&pVt, g_Vt);
    cudaGetSymbolAddress(&pCtxH, g_ctx_h);

    cudaFuncSetAttribute(gemm_qkv,
                         cudaFuncAttributeMaxDynamicSharedMemorySize, GEMM_SMEM);
    cudaFuncSetAttribute(gemm_out,
                         cudaFuncAttributeMaxDynamicSharedMemorySize, GEMM_SMEM);
    cudaFuncSetAttribute(attn_mma,
                         cudaFuncAttributeMaxDynamicSharedMemorySize, SMEM_ATTN);

    const int nBig4 = MROWS * DMODEL / 4;
    const int nW4 = DMODEL * DMODEL / 4;
    cvt_f32_f16<<<512, 256>>>(queries, (__half*)phA, nBig4);
    cvt_f32_f16<<<512, 256>>>(keys,    (__half*)phB, nBig4);
    cvt4_f32_f16<<<dim3(128, 4), 256>>>(Wq, Wk, Wv, Wo,
                                        (__half*)phWq, (__half*)phWk,
                                        (__half*)phWv, (__half*)phWo, nW4);

    gemm_qkv<<<dim3(MROWS / 128, DMODEL / 128, 3), 256, GEMM_SMEM>>>(
        (const __half*)phA, (const __half*)phB,
        (const __half*)phWq, (const __half*)phWk, (const __half*)phWv,
        (__half*)pQh, (__half*)pKh, (__half*)pVt);

    attn_mma<<<dim3(LEN / 128, BATCH, NH), 256, SMEM_ATTN>>>(seqlen);

    gemm_out<<<dim3(MROWS / 128, DMODEL / 128), 256, GEMM_SMEM>>>(
        (const __half*)pCtxH, (const __half*)phWo, out);
}

// round 17
// speedup vs baseline: 1.5940x; 1.0354x over previous
#include <cuda_runtime.h>
#include <cuda_fp16.h>
#include <cstdint>
#include <math.h>

#define BATCH 4
#define LEN 2048
#define DMODEL 1024
#define NH 8
#define DHEAD 128
#define MROWS (BATCH * LEN)

// fp16 GEMM operands
__device__ __half g_hA[MROWS * DMODEL];
__device__ __half g_hB[MROWS * DMODEL];
__device__ __half g_hWq[DMODEL * DMODEL];
__device__ __half g_hWk[DMODEL * DMODEL];
__device__ __half g_hWv[DMODEL * DMODEL];
__device__ __half g_hWo[DMODEL * DMODEL];
// fp16 attention operands
__device__ __half g_Qh[NH * BATCH * LEN * DHEAD];   // [h][b][l][d], pre-scaled
__device__ __half g_Kh[NH * BATCH * LEN * DHEAD];   // [h][b][l][d]
__device__ __half g_Vt[NH * BATCH * DHEAD * LEN];   // [h][b][d][l] transposed
__device__ __half g_ctx_h[BATCH * LEN * DMODEL];    // [b][l][h*128+d]

#define QSCL 0.08838834764831845f

// ---------------------------------------------------------------------------
__device__ __forceinline__ void mma_f16(float& d0, float& d1, float& d2,
                                        float& d3, uint32_t a0, uint32_t a1,
                                        uint32_t a2, uint32_t a3, uint32_t b0,
                                        uint32_t b1) {
    asm volatile(
        "mma.sync.aligned.m16n8k16.row.col.f32.f16.f16.f32 "
        "{%0,%1,%2,%3}, {%4,%5,%6,%7}, {%8,%9}, {%0,%1,%2,%3};"
        : "+f"(d0), "+f"(d1), "+f"(d2), "+f"(d3)
        : "r"(a0), "r"(a1), "r"(a2), "r"(a3), "r"(b0), "r"(b1));
}

__device__ __forceinline__ void ldsm_x4(uint32_t& r0, uint32_t& r1,
                                        uint32_t& r2, uint32_t& r3,
                                        uint32_t addr) {
    asm volatile(
        "ldmatrix.sync.aligned.m8n8.x4.shared.b16 {%0,%1,%2,%3}, [%4];"
        : "=r"(r0), "=r"(r1), "=r"(r2), "=r"(r3) : "r"(addr));
}

__device__ __forceinline__ uint32_t smem_u32(const void* p) {
    uint32_t a;
    asm("{ .reg .u64 t; cvta.to.shared.u64 t, %1; cvt.u32.u64 %0, t; }"
        : "=r"(a) : "l"(p));
    return a;
}

__device__ __forceinline__ uint32_t pack_h2(float a, float b) {
    const __half2 h = __floats2half2_rn(a, b);
    return *(const uint32_t*)&h;
}

#define CP_ASYNC16(dst_u32, src_ptr)                                          \
    asm volatile("cp.async.cg.shared.global [%0], [%1], 16;"                  \
                 :: "r"(dst_u32), "l"(src_ptr) : "memory")
#define CP_COMMIT() asm volatile("cp.async.commit_group;" ::: "memory")
#define CP_WAIT(n)  asm volatile("cp.async.wait_group %0;" :: "n"(n) : "memory")

// ===========================================================================
__global__ void __launch_bounds__(256)
cvt_f32_f16(const float* __restrict__ src, __half* __restrict__ dst, int n4)
{
    const int stride = gridDim.x * blockDim.x;
    for (int i = blockIdx.x * blockDim.x + threadIdx.x; i < n4; i += stride) {
        const float4 v = *(const float4*)(src + i * 4);
        __half2* d = (__half2*)(dst + i * 4);
        d[0] = __floats2half2_rn(v.x, v.y);
        d[1] = __floats2half2_rn(v.z, v.w);
    }
}

__global__ void __launch_bounds__(256)
cvt4_f32_f16(const float* __restrict__ s0, const float* __restrict__ s1,
             const float* __restrict__ s2, const float* __restrict__ s3,
             __half* __restrict__ d0, __half* __restrict__ d1,
             __half* __restrict__ d2, __half* __restrict__ d3, int n4)
{
    const float* src = blockIdx.y == 0 ? s0 : blockIdx.y == 1 ? s1
                     : blockIdx.y == 2 ? s2 : s3;
    __half* dst = blockIdx.y == 0 ? d0 : blockIdx.y == 1 ? d1
                : blockIdx.y == 2 ? d2 : d3;
    const int stride = gridDim.x * blockDim.x;
    for (int i = blockIdx.x * blockDim.x + threadIdx.x; i < n4; i += stride) {
        const float4 v = *(const float4*)(src + i * 4);
        __half2* d = (__half2*)(dst + i * 4);
        d[0] = __floats2half2_rn(v.x, v.y);
        d[1] = __floats2half2_rn(v.z, v.w);
    }
}

// ===========================================================================
// Shared GEMM mainloop: R14/R16 structure + FRAGMENT DOUBLE BUFFERING.
// CTA 128x128x32, 8 warps (2m x 4n), 3-stage cp.async ring.
// ===========================================================================
#define HSP 20
#define HSTG (128 * HSP)                 // u32 per operand per stage
#define HNIT (DMODEL / 32)               // 32
#define NSTG 3
#define GEMM_SMEM (NSTG * 2 * HSTG * (int)sizeof(uint32_t))   // 61440 B
#define TPITCH 136

struct Frags {
    uint32_t af[4][4];
    uint32_t bf[4][2];
};

__device__ __forceinline__ void load_frags(
    Frags& F, uint32_t sA, uint32_t sW, int wm, int wn, int ks,
    int lx, int lhiA, int l8, int lgB, int lqB)
{
#pragma unroll
    for (int mt = 0; mt < 4; mt++) {
        const uint32_t a =
            sA + ((wm + mt * 16 + lx) * HSP + ks * 8 + lhiA) * 4;
        ldsm_x4(F.af[mt][0], F.af[mt][1], F.af[mt][2], F.af[mt][3], a);
    }
#pragma unroll
    for (int p = 0; p < 2; p++) {
        const uint32_t a =
            sW + ((wn + p * 16 + lgB + l8) * HSP + ks * 8 + lqB) * 4;
        ldsm_x4(F.bf[2 * p][0], F.bf[2 * p][1], F.bf[2 * p + 1][0],
                F.bf[2 * p + 1][1], a);
    }
}

__device__ __forceinline__ void mma_frags(float acc[4][4][4], const Frags& F)
{
#pragma unroll
    for (int mt = 0; mt < 4; mt++)
#pragma unroll
        for (int nt = 0; nt < 4; nt++)
            mma_f16(acc[mt][nt][0], acc[mt][nt][1], acc[mt][nt][2],
                    acc[mt][nt][3], F.af[mt][0], F.af[mt][1], F.af[mt][2],
                    F.af[mt][3], F.bf[nt][0], F.bf[nt][1]);
}

__device__ __forceinline__ void gemm_mainloop(
    const __half* __restrict__ A, const __half* __restrict__ W,
    uint32_t sb, int m0, int n0, int tid, float acc[4][4][4])
{
    const int wid = tid >> 5;
    const int lane = tid & 31;
    const int wm = (wid >> 2) * 64;
    const int wn = (wid & 3) * 32;
    const int lx = lane & 15;
    const int lhiA = (lane >> 4) * 4;
    const int l8 = lane & 7;
    const int lgB = (lane >> 4) * 8;
    const int lqB = ((lane >> 3) & 1) * 4;

    const int lrow = tid >> 1;
    const int lch = (tid & 1) * 2;

    const __half* Ag = A + (size_t)(m0 + lrow) * DMODEL + lch * 8;
    const __half* Wg = W + (size_t)(n0 + lrow) * DMODEL + lch * 8;
    const uint32_t dA0 = sb + (lrow * HSP + lch * 4) * 4;
    const uint32_t dW0 = sb + (HSTG + lrow * HSP + lch * 4) * 4;

#pragma unroll
    for (int pre = 0; pre < NSTG; pre++) {
        const int k0 = pre * 32;
        const uint32_t so = pre * 2 * HSTG * 4;
        CP_ASYNC16(dA0 + so, Ag + k0);
        CP_ASYNC16(dA0 + so + 16, Ag + k0 + 8);
        CP_ASYNC16(dW0 + so, Wg + k0);
        CP_ASYNC16(dW0 + so + 16, Wg + k0 + 8);
        CP_COMMIT();
    }

    // wait for stage 0, preload fragments of (it=0, ks=0)
    CP_WAIT(2);
    __syncthreads();

    Frags fr[2];
    load_frags(fr[0], sb, sb + HSTG * 4, wm, wn, 0,
               lx, lhiA, l8, lgB, lqB);

    int stg = 0;
    for (int it = 0; it < HNIT; it++) {
        const uint32_t sA = sb + (stg * 2 * HSTG) * 4;
        const uint32_t sW = sA + HSTG * 4;
        const int nstg = (stg + 1 == NSTG) ? 0 : stg + 1;
        const uint32_t sA1 = sb + (nstg * 2 * HSTG) * 4;
        const uint32_t sW1 = sA1 + HSTG * 4;

        // ks=0: prefetch ks=1 frags, then mma ks=0
        load_frags(fr[1], sA, sW, wm, wn, 1, lx, lhiA, l8, lgB, lqB);
        mma_frags(acc, fr[0]);

        // refill stage stg with tile it+NSTG (done reading it by end of iter;
        // the barrier below serializes refill vs this iteration's reads)
        __syncthreads();    // all warps finished ldsm from stage stg? NO —
        // NOTE: fr[1] already loaded from stg above; mma ks=1 below uses regs
        // only, so stg can be refilled now.
        const int nxt = it + NSTG;
        if (nxt < HNIT) {
            const int k0 = nxt * 32;
            const uint32_t so = stg * 2 * HSTG * 4;
            CP_ASYNC16(dA0 + so, Ag + k0);
            CP_ASYNC16(dA0 + so + 16, Ag + k0 + 8);
            CP_ASYNC16(dW0 + so, Wg + k0);
            CP_ASYNC16(dW0 + so + 16, Wg + k0 + 8);
        }
        CP_COMMIT();

        // ks=1: wait next stage ready + prefetch (it+1, ks=0), then mma ks=1
        if (it + 1 < HNIT) {
            CP_WAIT(2);          // stage nstg (tile it+1) complete
            __syncthreads();
            load_frags(fr[0], sA1, sW1, wm, wn, 0, lx, lhiA, l8, lgB, lqB);
        }
        mma_frags(acc, fr[1]);

        stg = nstg;
    }
}

// ===========================================================================
// Fused Q/K/V projection GEMM (R16): grid.z selects operand set.
// ===========================================================================
__global__ void __launch_bounds__(256, 2)
gemm_qkv(const __half* __restrict__ Aq, const __half* __restrict__ Ak,
         const __half* __restrict__ Wq, const __half* __restrict__ Wk,
         const __half* __restrict__ Wv,
         __half* __restrict__ Qh, __half* __restrict__ Kh,
         __half* __restrict__ Vt)
{
    extern __shared__ uint32_t sh[];
    const uint32_t sb = smem_u32(sh);

    const int tid = threadIdx.x;
    const int wid = tid >> 5;
    const int lane = tid & 31;
    const int wm = (wid >> 2) * 64;
    const int wn = (wid & 3) * 32;
    const int r = lane >> 2;
    const int c = lane & 3;
    const int m0 = blockIdx.x * 128;
    const int n0 = blockIdx.y * 128;
    const int z = blockIdx.z;

    const __half* A = (z == 0) ? Aq : Ak;
    const __half* W = (z == 0) ? Wq : (z == 1) ? Wk : Wv;

    float acc[4][4][4];
#pragma unroll
    for (int i = 0; i < 4; i++)
#pragma unroll
        for (int j = 0; j < 4; j++)
#pragma unroll
            for (int q = 0; q < 4; q++) acc[i][j][q] = 0.0f;

    gemm_mainloop(A, W, sb, m0, n0, tid, acc);

    const int hh = n0 >> 7;
    const int bb = m0 >> 11;

    if (z == 2) {
        CP_WAIT(0);
        __syncthreads();
        __half* ts = (__half*)sh;
#pragma unroll
        for (int mt = 0; mt < 4; mt++) {
#pragma unroll
            for (int half = 0; half < 2; half++) {
                const int ml = wm + mt * 16 + r + half * 8;
#pragma unroll
                for (int nt = 0; nt < 4; nt++) {
                    const int ncol = wn + nt * 8 + 2 * c;
                    ts[ncol * TPITCH + ml] =
                        __float2half_rn(acc[mt][nt][half * 2]);
                    ts[(ncol + 1) * TPITCH + ml] =
                        __float2half_rn(acc[mt][nt][half * 2 + 1]);
                }
            }
        }
        __syncthreads();
        const int ll0 = m0 & (LEN - 1);
        __half* base = Vt + (size_t)(hh * BATCH + bb) * DHEAD * LEN;
#pragma unroll
        for (int it = 0; it < 8; it++) {
            const int f = tid + it * 256;
            const int d = f >> 4;
            const int ch = f & 15;
            const uint4 v = *(const uint4*)(ts + d * TPITCH + ch * 8);
            *(uint4*)(base + (size_t)d * LEN + ll0 + ch * 8) = v;
        }
        return;
    }

    const float scl = (z == 0) ? QSCL : 1.0f;
    __half* C = (z == 0) ? Qh : Kh;
#pragma unroll
    for (int mt = 0; mt < 4; mt++) {
#pragma unroll
        for (int half = 0; half < 2; half++) {
            const int mrow = m0 + wm + mt * 16 + r + half * 8;
            const int ll = mrow & (LEN - 1);
            __half* dst =
                C + (((size_t)(hh * BATCH + bb) * LEN + ll) << 7);
#pragma unroll
            for (int nt = 0; nt < 4; nt++) {
                const int ncol = wn + nt * 8 + 2 * c;
                *(__half2*)(dst + ncol) = __floats2half2_rn(
                    acc[mt][nt][half * 2] * scl,
                    acc[mt][nt][half * 2 + 1] * scl);
            }
        }
    }
}

// Final GEMM: out = ctx @ Wo^T, fp32 row-major.
__global__ void __launch_bounds__(256, 2)
gemm_out(const __half* __restrict__ A, const __half* __restrict__ W,
         float* __restrict__ C)
{
    extern __shared__ uint32_t sh[];
    const uint32_t sb = smem_u32(sh);

    const int tid = threadIdx.x;
    const int wid = tid >> 5;
    const int lane = tid & 31;
    const int wm = (wid >> 2) * 64;
    const int wn = (wid & 3) * 32;
    const int r = lane >> 2;
    const int c = lane & 3;
    const int m0 = blockIdx.x * 128;
    const int n0 = blockIdx.y * 128;

    float acc[4][4][4];
#pragma unroll
    for (int i = 0; i < 4; i++)
#pragma unroll
        for (int j = 0; j < 4; j++)
#pragma unroll
            for (int q = 0; q < 4; q++) acc[i][j][q] = 0.0f;

    gemm_mainloop(A, W, sb, m0, n0, tid, acc);

#pragma unroll
    for (int mt = 0; mt < 4; mt++) {
#pragma unroll
        for (int half = 0; half < 2; half++) {
            const int mrow = m0 + wm + mt * 16 + r + half * 8;
            float* dst = C + (size_t)mrow * DMODEL + n0;
#pragma unroll
            for (int nt = 0; nt < 4; nt++) {
                const int ncol = wn + nt * 8 + 2 * c;
                *(float2*)(dst + ncol) = make_float2(
                    acc[mt][nt][half * 2], acc[mt][nt][half * 2 + 1]);
            }
        }
    }
}

// ===========================================================================
// Flash attention (exact R14/R16 version).
// ===========================================================================
#define KP2 68
#define VP2 36
#define STGH (64 * KP2 + 128 * VP2)
#define SMA_PS2 (2 * STGH)
#define SMA_TOT2 (SMA_PS2 + 128 * VP2)
#define SMEM_ATTN (SMA_TOT2 * (int)sizeof(uint32_t))

__global__ void __launch_bounds__(256)
attn_mma(const int* __restrict__ seq)
{
    extern __shared__ uint32_t sm[];
    const uint32_t sb = smem_u32(sm);
    uint32_t* Ps = sm + SMA_PS2;
    const uint32_t sbPs = sb + SMA_PS2 * 4;

    const int tid = threadIdx.x;
    const int wid = tid >> 5;
    const int lane = tid & 31;
    const int r = lane >> 2;
    const int c = lane & 3;
    const int qt = blockIdx.x, b = blockIdx.y, h = blockIdx.z;
    const int qbase = qt * 128;
    const int slen = seq[b];
    const int q0 = wid * 16;

    const int lx = lane & 15;
    const int lhiA = (lane >> 4) * 4;
    const int l8 = lane & 7;
    const int lgB = (lane >> 4) * 8;
    const int lqB = ((lane >> 3) & 1) * 4;

    __half* ctx = g_ctx_h + (size_t)b * LEN * DMODEL + (size_t)h * DHEAD;

    if (qbase >= slen) {
#pragma unroll
        for (int it = 0; it < 8; it++) {
            const int f = tid + it * 256;
            const int row = f >> 4;
            const int cu = (f & 15) * 8;
            *(uint4*)(ctx + (size_t)(qbase + row) * DMODEL + cu) =
                make_uint4(0, 0, 0, 0);
        }
        return;
    }

    const __half* Qg = g_Qh + (((size_t)h * BATCH + b) * LEN + qbase) * DHEAD;
    const __half* Kg = g_Kh + ((size_t)h * BATCH + b) * LEN * DHEAD;
    const __half* Vg = g_Vt + ((size_t)h * BATCH + b) * DHEAD * LEN;

    const int nkt = (slen + 63) >> 6;

#pragma unroll
    for (int it = 0; it < 8; it++) {
        const int f = tid + it * 256;
        const int row = f >> 4;
        const int ch = f & 15;
        CP_ASYNC16(sb + (row * KP2 + ch * 4) * 4,
                   Qg + (size_t)row * DHEAD + ch * 8);
    }
    CP_COMMIT();
    CP_WAIT(0);
    __syncthreads();

    uint32_t qf[8][4];
#pragma unroll
    for (int ks = 0; ks < 8; ks++) {
        const uint32_t a = sb + ((q0 + lx) * KP2 + ks * 8 + lhiA) * 4;
        ldsm_x4(qf[ks][0], qf[ks][1], qf[ks][2], qf[ks][3], a);
    }
    __syncthreads();

#pragma unroll 1
    for (int pre = 0; pre < 2; pre++) {
        if (pre < nkt) {
            const int kb = pre * 64;
            const uint32_t kbase = sb + (pre * STGH) * 4;
            const uint32_t vbase = kbase + (64 * KP2) * 4;
#pragma unroll
            for (int it = 0; it < 4; it++) {
                const int f = tid + it * 256;
                const int row = f >> 4;
                const int ch = f & 15;
                CP_ASYNC16(kbase + (row * KP2 + ch * 4) * 4,
                           Kg + (size_t)(kb + row) * DHEAD + ch * 8);
            }
#pragma unroll
            for (int it = 0; it < 4; it++) {
                const int f = tid + it * 256;
                const int d = f >> 3;
                const int ch = f & 7;
                CP_ASYNC16(vbase + (d * VP2 + ch * 4) * 4,
                           Vg + (size_t)d * LEN + kb + ch * 8);
            }
        }
        CP_COMMIT();
    }

    float o[16][4];
#pragma unroll
    for (int nt = 0; nt < 16; nt++)
#pragma unroll
        for (int q = 0; q < 4; q++) o[nt][q] = 0.0f;
    float m0v = -1e30f, m1v = -1e30f, l0 = 0.0f, l1 = 0.0f;

    for (int kt = 0; kt < nkt; kt++) {
        const int kb = kt * 64;
        const int stg = kt & 1;
        const uint32_t sK = sb + (stg * STGH) * 4;
        const uint32_t sV = sK + (64 * KP2) * 4;

        CP_WAIT(1);
        __syncthreads();

        float s[8][4];
#pragma unroll
        for (int nt = 0; nt < 8; nt++)
#pragma unroll
            for (int q = 0; q < 4; q++) s[nt][q] = 0.0f;

#pragma unroll
        for (int ks = 0; ks < 8; ks++) {
            uint32_t bf[8][2];
#pragma unroll
            for (int p = 0; p < 4; p++) {
                const uint32_t a =
                    sK + ((p * 16 + lgB + l8) * KP2 + ks * 8 + lqB) * 4;
                ldsm_x4(bf[2 * p][0], bf[2 * p][1], bf[2 * p + 1][0],
                        bf[2 * p + 1][1], a);
            }
#pragma unroll
            for (int nt = 0; nt < 8; nt++)
                mma_f16(s[nt][0], s[nt][1], s[nt][2], s[nt][3],
                        qf[ks][0], qf[ks][1], qf[ks][2], qf[ks][3],
                        bf[nt][0], bf[nt][1]);
        }

#pragma unroll
        for (int nt = 0; nt < 8; nt++) {
            const int j0 = kb + nt * 8 + 2 * c;
            if (j0 >= slen)     { s[nt][0] = -1e30f; s[nt][2] = -1e30f; }
            if (j0 + 1 >= slen) { s[nt][1] = -1e30f; s[nt][3] = -1e30f; }
        }

        float mt0 = -1e30f, mt1 = -1e30f;
#pragma unroll
        for (int nt = 0; nt < 8; nt++) {
            mt0 = fmaxf(mt0, fmaxf(s[nt][0], s[nt][1]));
            mt1 = fmaxf(mt1, fmaxf(s[nt][2], s[nt][3]));
        }
        mt0 = fmaxf(mt0, __shfl_xor_sync(0xffffffffu, mt0, 1));
        mt0 = fmaxf(mt0, __shfl_xor_sync(0xffffffffu, mt0, 2));
        mt1 = fmaxf(mt1, __shfl_xor_sync(0xffffffffu, mt1, 1));
        mt1 = fmaxf(mt1, __shfl_xor_sync(0xffffffffu, mt1, 2));

        const float mn0 = fmaxf(m0v, mt0);
        const float mn1 = fmaxf(m1v, mt1);
        const float sc0 = __expf(m0v - mn0);
        const float sc1 = __expf(m1v - mn1);
        m0v = mn0; m1v = mn1;

        float rs0 = 0.0f, rs1 = 0.0f;
#pragma unroll
        for (int nt = 0; nt < 8; nt++) {
            const float p0 = __expf(s[nt][0] - mn0);
            const float p1 = __expf(s[nt][1] - mn0);
            const float p2 = __expf(s[nt][2] - mn1);
            const float p3 = __expf(s[nt][3] - mn1);
            rs0 += p0 + p1;
            rs1 += p2 + p3;
            Ps[(q0 + r) * VP2 + nt * 4 + c] = pack_h2(p0, p1);
            Ps[(q0 + r + 8) * VP2 + nt * 4 + c] = pack_h2(p2, p3);
        }
        rs0 += __shfl_xor_sync(0xffffffffu, rs0, 1);
        rs0 += __shfl_xor_sync(0xffffffffu, rs0, 2);
        rs1 += __shfl_xor_sync(0xffffffffu, rs1, 1);
        rs1 += __shfl_xor_sync(0xffffffffu, rs1, 2);
        l0 = l0 * sc0 + rs0;
        l1 = l1 * sc1 + rs1;

#pragma unroll
        for (int nt = 0; nt < 16; nt++) {
            o[nt][0] *= sc0; o[nt][1] *= sc0;
            o[nt][2] *= sc1; o[nt][3] *= sc1;
        }
        __syncwarp();

#pragma unroll
        for (int ks = 0; ks < 4; ks++) {
            uint32_t af[4];
            {
                const uint32_t a =
                    sbPs + ((q0 + lx) * VP2 + ks * 8 + lhiA) * 4;
                ldsm_x4(af[0], af[1], af[2], af[3], a);
            }
#pragma unroll
            for (int p = 0; p < 8; p++) {
                uint32_t b0a, b0b, b1a, b1b;
                const uint32_t a =
                    sV + ((p * 16 + lgB + l8) * VP2 + ks * 8 + lqB) * 4;
                ldsm_x4(b0a, b0b, b1a, b1b, a);
                mma_f16(o[2 * p][0], o[2 * p][1], o[2 * p][2], o[2 * p][3],
                        af[0], af[1], af[2], af[3], b0a, b0b);
                mma_f16(o[2 * p + 1][0], o[2 * p + 1][1], o[2 * p + 1][2],
                        o[2 * p + 1][3], af[0], af[1], af[2], af[3], b1a, b1b);
            }
        }

        __syncthreads();

        const int nxt = kt + 2;
        if (nxt < nkt) {
            const int kb2 = nxt * 64;
            const uint32_t kbase = sb + (stg * STGH) * 4;
            const uint32_t vbase = kbase + (64 * KP2) * 4;
#pragma unroll
            for (int it = 0; it < 4; it++) {
                const int f = tid + it * 256;
                const int row = f >> 4;
                const int ch = f & 15;
                CP_ASYNC16(kbase + (row * KP2 + ch * 4) * 4,
                           Kg + (size_t)(kb2 + row) * DHEAD + ch * 8);
            }
#pragma unroll
            for (int it = 0; it < 4; it++) {
                const int f = tid + it * 256;
                const int d = f >> 3;
                const int ch = f & 7;
                CP_ASYNC16(vbase + (d * VP2 + ch * 4) * 4,
                           Vg + (size_t)d * LEN + kb2 + ch * 8);
            }
        }
        CP_COMMIT();
    }

    const int qr0 = qbase + q0 + r;
    const int qr1 = qr0 + 8;
    const float inv0 = (qr0 < slen) ? (1.0f / l0) : 0.0f;
    const float inv1 = (qr1 < slen) ? (1.0f / l1) : 0.0f;
#pragma unroll
    for (int nt = 0; nt < 16; nt++) {
        const int col = nt * 8 + 2 * c;
        *(__half2*)(ctx + (size_t)qr0 * DMODEL + col) =
            __floats2half2_rn(o[nt][0] * inv0, o[nt][1] * inv0);
        *(__half2*)(ctx + (size_t)qr1 * DMODEL + col) =
            __floats2half2_rn(o[nt][2] * inv1, o[nt][3] * inv1);
    }
}

// ===========================================================================
extern "C" void kernel_launch(void* const* d_in, const int* in_sizes, int n_in,
                              void* d_out, int out_size)
{
    (void)in_sizes; (void)n_in; (void)out_size;
    const float* queries = (const float*)d_in[0];
    const float* keys    = (const float*)d_in[1];
    const int*   seqlen  = (const int*)d_in[2];
    const float* Wq      = (const float*)d_in[3];
    const float* Wk      = (const float*)d_in[4];
    const float* Wv      = (const float*)d_in[5];
    const float* Wo      = (const float*)d_in[6];
    float* out = (float*)d_out;

    void *phA, *phB, *phWq, *phWk, *phWv, *phWo, *pQh, *pKh, *pVt, *pCtxH;
    cudaGetSymbolAddress(&phA, g_hA);
    cudaGetSymbolAddress(&phB, g_hB);
    cudaGetSymbolAddress(&phWq, g_hWq);
    cudaGetSymbolAddress(&phWk, g_hWk);
    cudaGetSymbolAddress(&phWv, g_hWv);
    cudaGetSymbolAddress(&phWo, g_hWo);
    cudaGetSymbolAddress(&pQh, g_Qh);
    cudaGetSymbolAddress(&pKh, g_Kh);
    cudaGetSymbolAddress(&pVt, g_Vt);
    cudaGetSymbolAddress(&pCtxH, g_ctx_h);

    cudaFuncSetAttribute(gemm_qkv,
                         cudaFuncAttributeMaxDynamicSharedMemorySize, GEMM_SMEM);
    cudaFuncSetAttribute(gemm_out,
                         cudaFuncAttributeMaxDynamicSharedMemorySize, GEMM_SMEM);
    cudaFuncSetAttribute(attn_mma,
                         cudaFuncAttributeMaxDynamicSharedMemorySize, SMEM_ATTN);

    const int nBig4 = MROWS * DMODEL / 4;
    const int nW4 = DMODEL * DMODEL / 4;
    cvt_f32_f16<<<512, 256>>>(queries, (__half*)phA, nBig4);
    cvt_f32_f16<<<512, 256>>>(keys,    (__half*)phB, nBig4);
    cvt4_f32_f16<<<dim3(128, 4), 256>>>(Wq, Wk, Wv, Wo,
                                        (__half*)phWq, (__half*)phWk,
                                        (__half*)phWv, (__half*)phWo, nW4);

    gemm_qkv<<<dim3(MROWS / 128, DMODEL / 128, 3), 256, GEMM_SMEM>>>(
        (const __half*)phA, (const __half*)phB,
        (const __half*)phWq, (const __half*)phWk, (const __half*)phWv,
        (__half*)pQh, (__half*)pKh, (__half*)pVt);

    attn_mma<<<dim3(LEN / 128, BATCH, NH), 256, SMEM_ATTN>>>(seqlen);

    gemm_out<<<dim3(MROWS / 128, DMODEL / 128), 256, GEMM_SMEM>>>(
        (const __half*)pCtxH, (const __half*)phWo, out);
}